// round 14
// baseline (speedup 1.0000x reference)
#include <cuda_runtime.h>
#include <cstdint>

// probs: float32 [50,50,50,50] -> 6,250,000 floats (row-major)
// X:     int32   [8,000,000, 4]
// out:   float32 [8,000,000]
//
// out[i] = probs[ ((X0*50 + X1)*50 + X2)*50 + X3 ]
//
// Final calibration point on the gather issue-granularity curve:
//   full-warp LDG (32 lanes) : 45.7us profiled
//   quarter-warp   (8 lanes) : 44.6us -> 43.5us with cache ops (best so far)
//   half-warp     (16 lanes) : THIS KERNEL (untested midpoint)
// Half-warp halves gather instruction count vs quarter-warp while still
// splitting the divergent-address replay chain, trading replay-pipelining
// granularity for issue-slot savings. Everything else identical to the best
// config: __ldcg gathers / __ldcs X / __stcs out, UNROLL=4, 24 regs.

constexpr int THREADS = 256;
constexpr int UNROLL  = 4;
constexpr int TILE    = THREADS * UNROLL;  // 1024 samples per block

__global__ __launch_bounds__(THREADS) void joint_cat_gather_hw(
    const float* __restrict__ probs,
    const int4* __restrict__ X,
    float* __restrict__ out,
    int n)
{
    int base = blockIdx.x * TILE + threadIdx.x;
    int lane_group = (threadIdx.x & 31) >> 4;   // 0..1: lanes 0-15, 16-31

    if (base + (UNROLL - 1) * THREADS < n) {
        // ---- fast path: full tile ----
        int4 x[UNROLL];
#pragma unroll
        for (int k = 0; k < UNROLL; k++)
            x[k] = __ldcs(&X[base + k * THREADS]);     // streaming coalesced 16B loads

        int idx[UNROLL];
#pragma unroll
        for (int k = 0; k < UNROLL; k++)
            idx[k] = ((x[k].x * 50 + x[k].y) * 50 + x[k].z) * 50 + x[k].w;

        float r[UNROLL];
        // 8 predicated LDG.cg, each with 16 active lanes.
#pragma unroll
        for (int j = 0; j < 2; j++) {
#pragma unroll
            for (int k = 0; k < UNROLL; k++) {
                if (lane_group == j)
                    r[k] = __ldcg(probs + idx[k]);     // L2-only gather, no L1 fill
            }
        }

#pragma unroll
        for (int k = 0; k < UNROLL; k++)
            __stcs(&out[base + k * THREADS], r[k]);    // streaming coalesced stores
    } else {
        // ---- tail: per-element guard ----
#pragma unroll
        for (int k = 0; k < UNROLL; k++) {
            int i = base + k * THREADS;
            if (i < n) {
                int4 x = __ldcs(&X[i]);
                int idx = ((x.x * 50 + x.y) * 50 + x.z) * 50 + x.w;
                __stcs(&out[i], __ldcg(probs + idx));
            }
        }
    }
}

extern "C" void kernel_launch(void* const* d_in, const int* in_sizes, int n_in,
                              void* d_out, int out_size)
{
    const float* probs = (const float*)d_in[0];
    const int4* X = (const int4*)d_in[1];
    float* out = (float*)d_out;

    int n = out_size;  // 8,000,000 samples
    int blocks = (n + TILE - 1) / TILE;
    joint_cat_gather_hw<<<blocks, THREADS>>>(probs, X, out, n);
}

// round 15
// speedup vs baseline: 1.0758x; 1.0758x over previous
#include <cuda_runtime.h>
#include <cstdint>

// probs: float32 [50,50,50,50] -> 6,250,000 floats (row-major)
// X:     int32   [8,000,000, 4]
// out:   float32 [8,000,000]
//
// out[i] = probs[ ((X0*50 + X1)*50 + X2)*50 + X3 ]
//
// FINAL — optimum of the complete R2-R14 sweep (12 variants), 43.46us
// profiled, reproduced across three benches:
//  - quarter-warp predicated gathers (8 active lanes/LDG): completes the
//    measured issue-granularity curve — full-warp 45.7us, half-warp 45.5us,
//    quarter-warp 43.5us. Shorter divergent-address replay chains let L1tex
//    pipeline wavefronts across instructions.
//  - __ldcg gathers (L2-only, no L1 fill/pollution), __ldcs X (streaming),
//    __stcs out (streaming): measured win.
//  - UNROLL=4 at 24 regs -> ~88-90% occupancy; UNROLL=8 (34 regs, 68% occ)
//    measured strictly worse — warp-parallelism beats thread-ILP here.
//  - Falsified levers (neutral or regression): bulk-TMA X feed, persistent
//    double-buffered pipeline (-56%), cp.async gathers, L2 eviction-priority
//    policies, half-warp granularity.
//  - Binding constraint: L1tex/L2 service rate for 8M unsorted 4B gathers
//    (32B L2 sector each) at ~0.7 wf/cyc/SM, atop the ~170MB DRAM stream
//    floor. ~43.5us profiled is the hardware floor for this access pattern.

constexpr int THREADS = 256;
constexpr int UNROLL  = 4;
constexpr int TILE    = THREADS * UNROLL;  // 1024 samples per block

__global__ __launch_bounds__(THREADS) void joint_cat_gather_final(
    const float* __restrict__ probs,
    const int4* __restrict__ X,
    float* __restrict__ out,
    int n)
{
    int base = blockIdx.x * TILE + threadIdx.x;
    int lane_group = (threadIdx.x & 31) >> 3;   // 0..3

    if (base + (UNROLL - 1) * THREADS < n) {
        // ---- fast path: full tile ----
        int4 x[UNROLL];
#pragma unroll
        for (int k = 0; k < UNROLL; k++)
            x[k] = __ldcs(&X[base + k * THREADS]);     // streaming coalesced 16B loads

        int idx[UNROLL];
#pragma unroll
        for (int k = 0; k < UNROLL; k++)
            idx[k] = ((x[k].x * 50 + x[k].y) * 50 + x[k].z) * 50 + x[k].w;

        float r[UNROLL];
        // 16 predicated LDG.cg, each with 8 active lanes.
#pragma unroll
        for (int j = 0; j < 4; j++) {
#pragma unroll
            for (int k = 0; k < UNROLL; k++) {
                if (lane_group == j)
                    r[k] = __ldcg(probs + idx[k]);     // L2-only gather, no L1 fill
            }
        }

#pragma unroll
        for (int k = 0; k < UNROLL; k++)
            __stcs(&out[base + k * THREADS], r[k]);    // streaming coalesced stores
    } else {
        // ---- tail: per-element guard ----
#pragma unroll
        for (int k = 0; k < UNROLL; k++) {
            int i = base + k * THREADS;
            if (i < n) {
                int4 x = __ldcs(&X[i]);
                int idx = ((x.x * 50 + x.y) * 50 + x.z) * 50 + x.w;
                __stcs(&out[i], __ldcg(probs + idx));
            }
        }
    }
}

extern "C" void kernel_launch(void* const* d_in, const int* in_sizes, int n_in,
                              void* d_out, int out_size)
{
    const float* probs = (const float*)d_in[0];
    const int4* X = (const int4*)d_in[1];
    float* out = (float*)d_out;

    int n = out_size;  // 8,000,000 samples
    int blocks = (n + TILE - 1) / TILE;
    joint_cat_gather_final<<<blocks, THREADS>>>(probs, X, out, n);
}